// round 7
// baseline (speedup 1.0000x reference)
#include <cuda_runtime.h>

// Problem constants
#define TOK   197
#define NH    12
#define HD    64
#define CDIM  768
#define BATCH 64
#define MTOT  (BATCH * TOK)          // 12608 rows

// Attention smem layout constants
#define KSTR  68                     // 64 + 4 pad: float4 conflict-free (bank step 4)
#define PSTR  208
#define ATTN_SMEM_FLOATS (2 * TOK * KSTR + 8 * HD + 8 * PSTR)
#define ATTN_SMEM_BYTES  (ATTN_SMEM_FLOATS * 4)

// Scratch (no allocation allowed -> __device__ globals)
__device__ float g_qkv[(size_t)MTOT * (3 * CDIM)];   // 116.2 MB
__device__ float g_att[(size_t)MTOT * CDIM];         //  38.8 MB
__device__ float g_bias[3 * CDIM];
__device__ float g_rpb[(size_t)NH * TOK * TOK];      //  1.86 MB, batch-invariant

// ---------------------------------------------------------------------------
// Build concat(q_bias, 0, v_bias) bias vector for the QKV GEMM epilogue
// ---------------------------------------------------------------------------
__global__ void build_bias_kernel(const float* __restrict__ qb,
                                  const float* __restrict__ vb) {
    int i = blockIdx.x * blockDim.x + threadIdx.x;
    if (i < 3 * CDIM) {
        float v;
        if (i < CDIM)           v = qb[i];
        else if (i < 2 * CDIM)  v = 0.f;
        else                    v = vb[i - 2 * CDIM];
        g_bias[i] = v;
    }
}

// ---------------------------------------------------------------------------
// Densify RPB: g_rpb[h][i][j] = rpb_table[rel_idx[i*TOK+j] * NH + h]
// One thread per (i,j); 12 contiguous table reads, batch-invariant result.
// ---------------------------------------------------------------------------
__global__ void build_rpb_kernel(const float* __restrict__ rpb_table,
                                 const int* __restrict__ rel_idx) {
    int p = blockIdx.x * blockDim.x + threadIdx.x;
    if (p < TOK * TOK) {
        int idx = rel_idx[p];
        const float* src = rpb_table + (size_t)idx * NH;
#pragma unroll
        for (int h = 0; h < NH; h++)
            g_rpb[(size_t)h * TOK * TOK + p] = src[h];
    }
}

// ---------------------------------------------------------------------------
// C[M,N] = A[M,K] @ B[N,K]^T + bias[N]
// 128x128 tile, BK=8, 256 threads, 8x8 register micro-tile (4+4 split cols).
// Register prefetch + DOUBLE-BUFFERED smem: one __syncthreads per K-step.
// Bias float4s prefetched before the final compute block.
// ---------------------------------------------------------------------------
__global__ __launch_bounds__(256, 2)
void sgemm_nt_kernel(const float* __restrict__ A, const float* __restrict__ B,
                     const float* __restrict__ bias, float* __restrict__ C,
                     int M, int N, int K) {
    __shared__ float As[2][8][132];
    __shared__ float Bs[2][8][132];

    const int tid  = threadIdx.x;
    const int bm   = blockIdx.y * 128;
    const int bn   = blockIdx.x * 128;
    const int lrow = tid >> 1;            // 0..127
    const int lcol = (tid & 1) * 4;       // 0 or 4
    const int tx   = tid & 15;
    const int ty   = tid >> 4;

    float acc[8][8];
#pragma unroll
    for (int i = 0; i < 8; i++)
#pragma unroll
        for (int j = 0; j < 8; j++) acc[i][j] = 0.f;

    const bool aval = (bm + lrow) < M;    // N-dim tiles are always full (N % 128 == 0)
    const float* Ap = A + (size_t)(bm + lrow) * K + lcol;
    const float* Bp = B + (size_t)(bn + lrow) * K + lcol;

    // Prologue: load tile 0, commit into buffer 0
    float4 a4 = make_float4(0.f, 0.f, 0.f, 0.f);
    if (aval) a4 = *(const float4*)(Ap);
    float4 b4 = *(const float4*)(Bp);

    As[0][lcol + 0][lrow] = a4.x; As[0][lcol + 1][lrow] = a4.y;
    As[0][lcol + 2][lrow] = a4.z; As[0][lcol + 3][lrow] = a4.w;
    Bs[0][lcol + 0][lrow] = b4.x; Bs[0][lcol + 1][lrow] = b4.y;
    Bs[0][lcol + 2][lrow] = b4.z; Bs[0][lcol + 3][lrow] = b4.w;
    __syncthreads();

    int cur = 0;
    for (int k0 = 8; k0 < K; k0 += 8) {
        // Prefetch next K-tile from global (latency overlapped with compute)
        a4 = make_float4(0.f, 0.f, 0.f, 0.f);
        if (aval) a4 = *(const float4*)(Ap + k0);
        b4 = *(const float4*)(Bp + k0);

        // Compute on current buffer
#pragma unroll
        for (int kk = 0; kk < 8; kk++) {
            float ar[8], br[8];
            *(float4*)(ar)     = *(const float4*)(&As[cur][kk][ty * 4]);
            *(float4*)(ar + 4) = *(const float4*)(&As[cur][kk][ty * 4 + 64]);
            *(float4*)(br)     = *(const float4*)(&Bs[cur][kk][tx * 4]);
            *(float4*)(br + 4) = *(const float4*)(&Bs[cur][kk][tx * 4 + 64]);
#pragma unroll
            for (int i = 0; i < 8; i++)
#pragma unroll
                for (int j = 0; j < 8; j++)
                    acc[i][j] += ar[i] * br[j];
        }

        // Commit prefetched tile into the other buffer; single barrier
        int nxt = cur ^ 1;
        As[nxt][lcol + 0][lrow] = a4.x; As[nxt][lcol + 1][lrow] = a4.y;
        As[nxt][lcol + 2][lrow] = a4.z; As[nxt][lcol + 3][lrow] = a4.w;
        Bs[nxt][lcol + 0][lrow] = b4.x; Bs[nxt][lcol + 1][lrow] = b4.y;
        Bs[nxt][lcol + 2][lrow] = b4.z; Bs[nxt][lcol + 3][lrow] = b4.w;
        __syncthreads();
        cur = nxt;
    }

    // Prefetch bias for the epilogue (hidden behind the final compute block)
    float4 bia0 = *(const float4*)(&bias[bn + tx * 4]);
    float4 bia1 = *(const float4*)(&bias[bn + tx * 4 + 64]);

    // Epilogue compute on the final buffer
#pragma unroll
    for (int kk = 0; kk < 8; kk++) {
        float ar[8], br[8];
        *(float4*)(ar)     = *(const float4*)(&As[cur][kk][ty * 4]);
        *(float4*)(ar + 4) = *(const float4*)(&As[cur][kk][ty * 4 + 64]);
        *(float4*)(br)     = *(const float4*)(&Bs[cur][kk][tx * 4]);
        *(float4*)(br + 4) = *(const float4*)(&Bs[cur][kk][tx * 4 + 64]);
#pragma unroll
        for (int i = 0; i < 8; i++)
#pragma unroll
            for (int j = 0; j < 8; j++)
                acc[i][j] += ar[i] * br[j];
    }

#pragma unroll
    for (int i = 0; i < 8; i++) {
        int r = bm + ty * 4 + (i < 4 ? i : 60 + i);   // rows ty*4+i and 64+ty*4+(i-4)
        if (r < M) {
            float4 o0, o1;
            o0.x = acc[i][0] + bia0.x; o0.y = acc[i][1] + bia0.y;
            o0.z = acc[i][2] + bia0.z; o0.w = acc[i][3] + bia0.w;
            o1.x = acc[i][4] + bia1.x; o1.y = acc[i][5] + bia1.y;
            o1.z = acc[i][6] + bia1.z; o1.w = acc[i][7] + bia1.w;
            *(float4*)(&C[(size_t)r * N + bn + tx * 4])      = o0;
            *(float4*)(&C[(size_t)r * N + bn + tx * 4 + 64]) = o1;
        }
    }
}

// ---------------------------------------------------------------------------
// Fused attention: TWO CTAs per (batch, head) — interleaved query rows —
// to halve the tail-wave quantum at occupancy 1. K/V resident in smem.
// Per-warp rows: QK^T scores (float4 dots) + dense RPB -> softmax -> PV.
// ---------------------------------------------------------------------------
__global__ __launch_bounds__(256, 1)
void attn_kernel(const float* __restrict__ qkv,
                 float* __restrict__ out) {
    extern __shared__ float sm[];
    float* Ks = sm;                       // TOK * KSTR
    float* Vs = Ks + TOK * KSTR;          // TOK * KSTR
    float* Qs = Vs + TOK * KSTR;          // 8 * HD
    float* Ps = Qs + 8 * HD;              // 8 * PSTR

    const int bh   = blockIdx.x >> 1;     // (batch, head) pair
    const int half = blockIdx.x & 1;      // row-split: rows w+8*half, step 16
    const int b  = bh / NH;
    const int h  = bh % NH;
    const float* base = qkv + (size_t)b * TOK * (3 * CDIM);
    const float* rpbh = g_rpb + (size_t)h * TOK * TOK;
    const int tid = threadIdx.x;

    // Stage K and V tiles (197 x 64 each) into smem, float4, coalesced
    for (int idx = tid; idx < TOK * 16; idx += 256) {
        int n  = idx >> 4;
        int d4 = (idx & 15) << 2;
        const float* rowp = base + (size_t)n * (3 * CDIM) + h * HD + d4;
        float4 kk = *(const float4*)(rowp + CDIM);
        float4 vv = *(const float4*)(rowp + 2 * CDIM);
        *(float4*)(Ks + n * KSTR + d4) = kk;
        *(float4*)(Vs + n * KSTR + d4) = vv;
    }
    __syncthreads();

    const int w    = tid >> 5;
    const int lane = tid & 31;

    for (int i = w + 8 * half; i < TOK; i += 16) {
        // Stage scaled q row (scale = hd^-0.5 = 0.125); two independent loads
        const float* qrow = base + (size_t)i * (3 * CDIM) + h * HD;
        float q0 = qrow[lane];
        float q1 = qrow[lane + 32];
        Qs[w * HD + lane]      = q0 * 0.125f;
        Qs[w * HD + lane + 32] = q1 * 0.125f;
        __syncwarp();

        // Scores: each lane owns columns j = lane + 32t; dense RPB row is
        // linear + coalesced (L2-resident 1.86 MB table).
        const float* rpbrow = rpbh + (size_t)i * TOK;
        float s[7];
#pragma unroll
        for (int t = 0; t < 7; t++) {
            int j = lane + t * 32;
            float a = -3.0e38f;
            if (j < TOK) {
                const float4* kp = (const float4*)(Ks + j * KSTR);
                const float4* qp = (const float4*)(Qs + w * HD);
                float4 accv = make_float4(0.f, 0.f, 0.f, 0.f);
#pragma unroll
                for (int d = 0; d < 16; d++) {
                    float4 k4 = kp[d];
                    float4 q4 = qp[d];
                    accv.x += q4.x * k4.x;
                    accv.y += q4.y * k4.y;
                    accv.z += q4.z * k4.z;
                    accv.w += q4.w * k4.w;
                }
                a = (accv.x + accv.y) + (accv.z + accv.w) + rpbrow[j];
            }
            s[t] = a;
        }

        // Softmax (warp-wide)
        float m = s[0];
#pragma unroll
        for (int t = 1; t < 7; t++) m = fmaxf(m, s[t]);
#pragma unroll
        for (int o = 16; o > 0; o >>= 1) m = fmaxf(m, __shfl_xor_sync(0xffffffffu, m, o));

        float sum = 0.f;
#pragma unroll
        for (int t = 0; t < 7; t++) {
            int j = lane + t * 32;
            float e = (j < TOK) ? __expf(s[t] - m) : 0.f;
            s[t] = e;
            sum += e;
        }
#pragma unroll
        for (int o = 16; o > 0; o >>= 1) sum += __shfl_xor_sync(0xffffffffu, sum, o);
        float inv = __frcp_rn(sum);

#pragma unroll
        for (int t = 0; t < 7; t++) {
            int j = lane + t * 32;
            if (j < TOK) Ps[w * PSTR + j] = s[t] * inv;
        }
        __syncwarp();

        // PV: lane owns dims {lane, lane+32}; 8 independent FMA chains (4-way unroll)
        float a0 = 0.f, a1 = 0.f, b0 = 0.f, b1 = 0.f;
        float c0 = 0.f, c1 = 0.f, d0 = 0.f, d1 = 0.f;
        int j = 0;
        for (; j + 3 < TOK; j += 4) {
            float p0 = Ps[w * PSTR + j];
            float p1 = Ps[w * PSTR + j + 1];
            float p2 = Ps[w * PSTR + j + 2];
            float p3 = Ps[w * PSTR + j + 3];
            a0 += p0 * Vs[j * KSTR + lane];
            a1 += p0 * Vs[j * KSTR + lane + 32];
            b0 += p1 * Vs[(j + 1) * KSTR + lane];
            b1 += p1 * Vs[(j + 1) * KSTR + lane + 32];
            c0 += p2 * Vs[(j + 2) * KSTR + lane];
            c1 += p2 * Vs[(j + 2) * KSTR + lane + 32];
            d0 += p3 * Vs[(j + 3) * KSTR + lane];
            d1 += p3 * Vs[(j + 3) * KSTR + lane + 32];
        }
        for (; j < TOK; j++) {
            float p = Ps[w * PSTR + j];
            a0 += p * Vs[j * KSTR + lane];
            a1 += p * Vs[j * KSTR + lane + 32];
        }
        a0 += b0 + c0 + d0;
        a1 += b1 + c1 + d1;

        float* orow = out + ((size_t)b * TOK + i) * CDIM + h * HD;
        orow[lane]      = a0;
        orow[lane + 32] = a1;
        __syncwarp();
    }
}

// ---------------------------------------------------------------------------
// kernel_launch: bias+RPB prep -> QKV GEMM -> fused attention -> proj GEMM
// ---------------------------------------------------------------------------
extern "C" void kernel_launch(void* const* d_in, const int* in_sizes, int n_in,
                              void* d_out, int out_size) {
    const float* x      = (const float*)d_in[0];
    const float* qkv_w  = (const float*)d_in[1];
    const float* q_bias = (const float*)d_in[2];
    const float* v_bias = (const float*)d_in[3];
    const float* rpb    = (const float*)d_in[4];
    const float* proj_w = (const float*)d_in[5];
    const float* proj_b = (const float*)d_in[6];
    const int*   relidx = (const int*)d_in[7];
    float* out = (float*)d_out;

    void* qkv_ptr;  cudaGetSymbolAddress(&qkv_ptr,  g_qkv);
    void* att_ptr;  cudaGetSymbolAddress(&att_ptr,  g_att);
    void* bias_ptr; cudaGetSymbolAddress(&bias_ptr, g_bias);

    // 1. Fused bias vector + dense RPB table (both tiny)
    build_bias_kernel<<<(3 * CDIM + 255) / 256, 256>>>(q_bias, v_bias);
    build_rpb_kernel<<<(TOK * TOK + 255) / 256, 256>>>(rpb, relidx);

    // 2. QKV GEMM: (12608 x 768) @ (2304 x 768)^T + bias
    {
        dim3 grid((3 * CDIM) / 128, (MTOT + 127) / 128);
        sgemm_nt_kernel<<<grid, 256>>>(x, qkv_w, (const float*)bias_ptr,
                                       (float*)qkv_ptr, MTOT, 3 * CDIM, CDIM);
    }

    // 3. Fused attention (1536 CTAs = B*H*2 row-halves)
    cudaFuncSetAttribute(attn_kernel, cudaFuncAttributeMaxDynamicSharedMemorySize,
                         ATTN_SMEM_BYTES);
    attn_kernel<<<BATCH * NH * 2, 256, ATTN_SMEM_BYTES>>>((const float*)qkv_ptr,
                                                          (float*)att_ptr);

    // 4. Proj GEMM: (12608 x 768) @ (768 x 768)^T + proj_b
    {
        dim3 grid(CDIM / 128, (MTOT + 127) / 128);
        sgemm_nt_kernel<<<grid, 256>>>((const float*)att_ptr, proj_w, proj_b,
                                       out, MTOT, CDIM, CDIM);
    }
}

// round 16
// speedup vs baseline: 1.6973x; 1.6973x over previous
#include <cuda_runtime.h>
#include <cstdint>

// Problem constants
#define TOK   197
#define NH    12
#define HD    64
#define CDIM  768
#define BATCH 64
#define MTOT  (BATCH * TOK)          // 12608 rows

// Attention smem layout constants (512 threads = 16 warps)
#define KSTR  68                     // 64 + 4 pad: float4 conflict-free
#define PSTR  208
#define ATTN_SMEM_FLOATS (2 * TOK * KSTR + 16 * HD + 16 * PSTR)
#define ATTN_SMEM_BYTES  (ATTN_SMEM_FLOATS * 4)

// tf32 GEMM tile config
#define BM 128
#define BN 128
#define BKT 32
#define ASTR 36                      // padded smem row stride (floats): 16B-aligned float4s,
                                     // banks (4g+t) conflict-free for mma fragment reads
#define GEMM_SMEM_BYTES (2 * 2 * 128 * ASTR * 4)   // 2 buf x (A+B) x 128x36 fl = 73728 B

// Scratch (no allocation allowed -> __device__ globals)
__device__ float g_qkv[(size_t)MTOT * (3 * CDIM)];   // 116.2 MB
__device__ float g_att[(size_t)MTOT * CDIM];         //  38.8 MB
__device__ float g_bias[3 * CDIM];
__device__ float g_rpb[(size_t)NH * TOK * TOK];      //  1.86 MB, batch-invariant

// ---------------------------------------------------------------------------
// PTX helpers
// ---------------------------------------------------------------------------
#define CP_ASYNC16(dst32, src, pbytes) \
    asm volatile("cp.async.ca.shared.global [%0], [%1], 16, %2;\n" \
                 :: "r"(dst32), "l"(src), "r"(pbytes) : "memory")
#define CP_COMMIT()  asm volatile("cp.async.commit_group;\n" ::: "memory")
#define CP_WAIT1()   asm volatile("cp.async.wait_group 1;\n" ::: "memory")
#define CP_WAIT0()   asm volatile("cp.async.wait_group 0;\n" ::: "memory")
#define F2TF32(u, f) asm volatile("cvt.rna.tf32.f32 %0, %1;\n" : "=r"(u) : "f"(f))
#define MMA_TF32(c, a, b) \
    asm volatile("mma.sync.aligned.m16n8k8.row.col.f32.tf32.tf32.f32 " \
                 "{%0,%1,%2,%3}, {%4,%5,%6,%7}, {%8,%9}, {%0,%1,%2,%3};\n" \
                 : "+f"((c)[0]), "+f"((c)[1]), "+f"((c)[2]), "+f"((c)[3]) \
                 : "r"((a)[0]), "r"((a)[1]), "r"((a)[2]), "r"((a)[3]), \
                   "r"((b)[0]), "r"((b)[1]))

// ---------------------------------------------------------------------------
// Build concat(q_bias, 0, v_bias) bias vector for the QKV GEMM epilogue
// ---------------------------------------------------------------------------
__global__ void build_bias_kernel(const float* __restrict__ qb,
                                  const float* __restrict__ vb) {
    int i = blockIdx.x * blockDim.x + threadIdx.x;
    if (i < 3 * CDIM) {
        float v;
        if (i < CDIM)           v = qb[i];
        else if (i < 2 * CDIM)  v = 0.f;
        else                    v = vb[i - 2 * CDIM];
        g_bias[i] = v;
    }
}

// ---------------------------------------------------------------------------
// Densify RPB: g_rpb[h][i][j] = rpb_table[rel_idx[i*TOK+j] * NH + h]
// ---------------------------------------------------------------------------
__global__ void build_rpb_kernel(const float* __restrict__ rpb_table,
                                 const int* __restrict__ rel_idx) {
    int p = blockIdx.x * blockDim.x + threadIdx.x;
    if (p < TOK * TOK) {
        int idx = rel_idx[p];
        const float* src = rpb_table + (size_t)idx * NH;
#pragma unroll
        for (int h = 0; h < NH; h++)
            g_rpb[(size_t)h * TOK * TOK + p] = src[h];
    }
}

// ---------------------------------------------------------------------------
// tf32 tensor-core GEMM: C[M,N] = A[M,K] @ B[N,K]^T + bias[N]
// 128x128 CTA tile, 8 warps (2M x 4N), warp tile 64x32, mma.m16n8k8.
// cp.async double-buffered smem (BK=32), cvt.rna.tf32 on fragment load.
// Requires N % 128 == 0, K % 32 == 0 (holds: N in {2304,768}, K=768).
// ---------------------------------------------------------------------------
__global__ __launch_bounds__(256, 1)
void tgemm_nt_kernel(const float* __restrict__ A, const float* __restrict__ B,
                     const float* __restrict__ bias, float* __restrict__ C,
                     int M, int N, int K) {
    extern __shared__ float smem[];
    float* As = smem;                     // [2][128][ASTR]
    float* Bs = smem + 2 * 128 * ASTR;    // [2][128][ASTR]

    const int tid  = threadIdx.x;
    const int bm   = blockIdx.y * BM;
    const int bn   = blockIdx.x * BN;
    const int warp = tid >> 5;
    const int lane = tid & 31;
    const int wm   = warp >> 2;           // 0..1
    const int wn   = warp & 3;            // 0..3
    const int g    = lane >> 2;           // 0..7
    const int t    = lane & 3;            // 0..3

    float acc[4][4][4];
#pragma unroll
    for (int i = 0; i < 4; i++)
#pragma unroll
        for (int j = 0; j < 4; j++)
#pragma unroll
            for (int r = 0; r < 4; r++) acc[i][j][r] = 0.f;

    const uint32_t sA = (uint32_t)__cvta_generic_to_shared(As);
    const uint32_t sB = (uint32_t)__cvta_generic_to_shared(Bs);

    const int NIT = K / BKT;              // 24

    // ---- async tile loader: 4 x 16B per thread per matrix ----
#define ISSUE_TILE(buf, k0)                                                  \
    {                                                                        \
        _Pragma("unroll")                                                    \
        for (int c = 0; c < 4; c++) {                                        \
            int idx  = c * 256 + tid;                                        \
            int row  = idx >> 3;                                             \
            int col4 = (idx & 7) * 4;                                        \
            int gr   = bm + row;                                             \
            const float* srcA = A + (size_t)(gr < M ? gr : 0) * K + (k0) + col4; \
            uint32_t dstA = sA + (((buf) * 128 + row) * ASTR + col4) * 4;    \
            CP_ASYNC16(dstA, srcA, (gr < M) ? 16 : 0);                       \
            const float* srcB = B + (size_t)(bn + row) * K + (k0) + col4;    \
            uint32_t dstB = sB + (((buf) * 128 + row) * ASTR + col4) * 4;    \
            CP_ASYNC16(dstB, srcB, 16);                                      \
        }                                                                    \
        CP_COMMIT();                                                         \
    }

    ISSUE_TILE(0, 0);

    int buf = 0;
    for (int it = 0; it < NIT; it++) {
        if (it + 1 < NIT) {
            ISSUE_TILE(buf ^ 1, (it + 1) * BKT);
            CP_WAIT1();
        } else {
            CP_WAIT0();
        }
        __syncthreads();

        const float* Ab = As + buf * 128 * ASTR;
        const float* Bb = Bs + buf * 128 * ASTR;
#pragma unroll
        for (int ak = 0; ak < 4; ak++) {
            uint32_t af[4][4];
#pragma unroll
            for (int am = 0; am < 4; am++) {
                int r0 = wm * 64 + am * 16 + g;
                int c0 = ak * 8 + t;
                F2TF32(af[am][0], Ab[r0 * ASTR + c0]);
                F2TF32(af[am][1], Ab[(r0 + 8) * ASTR + c0]);
                F2TF32(af[am][2], Ab[r0 * ASTR + c0 + 4]);
                F2TF32(af[am][3], Ab[(r0 + 8) * ASTR + c0 + 4]);
            }
            uint32_t bf[4][2];
#pragma unroll
            for (int an = 0; an < 4; an++) {
                int n0 = wn * 32 + an * 8 + g;
                int c0 = ak * 8 + t;
                F2TF32(bf[an][0], Bb[n0 * ASTR + c0]);
                F2TF32(bf[an][1], Bb[n0 * ASTR + c0 + 4]);
            }
#pragma unroll
            for (int am = 0; am < 4; am++)
#pragma unroll
                for (int an = 0; an < 4; an++)
                    MMA_TF32(acc[am][an], af[am], bf[an]);
        }
        __syncthreads();
        buf ^= 1;
    }

    // ---- epilogue: + bias, float2 stores ----
#pragma unroll
    for (int am = 0; am < 4; am++) {
        int row0 = bm + wm * 64 + am * 16 + g;
        int row1 = row0 + 8;
#pragma unroll
        for (int an = 0; an < 4; an++) {
            int col = bn + wn * 32 + an * 8 + t * 2;
            float bx = bias[col], by = bias[col + 1];
            if (row0 < M) {
                float2 o; o.x = acc[am][an][0] + bx; o.y = acc[am][an][1] + by;
                *(float2*)(&C[(size_t)row0 * N + col]) = o;
            }
            if (row1 < M) {
                float2 o; o.x = acc[am][an][2] + bx; o.y = acc[am][an][3] + by;
                *(float2*)(&C[(size_t)row1 * N + col]) = o;
            }
        }
    }
}

// ---------------------------------------------------------------------------
// Fused attention: TWO CTAs per (batch, head) — interleaved query rows — to
// halve the tail-wave quantum at occupancy 1. 512 threads (16 warps) per CTA.
// K/V resident in smem. Per-warp rows: QK^T scores + dense RPB -> softmax -> PV.
// ---------------------------------------------------------------------------
__global__ __launch_bounds__(512, 1)
void attn_kernel(const float* __restrict__ qkv,
                 float* __restrict__ out) {
    extern __shared__ float sm[];
    float* Ks = sm;                       // TOK * KSTR
    float* Vs = Ks + TOK * KSTR;          // TOK * KSTR
    float* Qs = Vs + TOK * KSTR;          // 16 * HD
    float* Ps = Qs + 16 * HD;             // 16 * PSTR

    const int bh   = blockIdx.x >> 1;     // (batch, head) pair
    const int half = blockIdx.x & 1;      // row split: i = w + 16*half, step 32
    const int b  = bh / NH;
    const int h  = bh % NH;
    const float* base = qkv + (size_t)b * TOK * (3 * CDIM);
    const float* rpbh = g_rpb + (size_t)h * TOK * TOK;
    const int tid = threadIdx.x;

    // Stage K and V tiles (197 x 64 each) into smem, float4, coalesced
    for (int idx = tid; idx < TOK * 16; idx += 512) {
        int n  = idx >> 4;
        int d4 = (idx & 15) << 2;
        const float* rowp = base + (size_t)n * (3 * CDIM) + h * HD + d4;
        float4 kk = *(const float4*)(rowp + CDIM);
        float4 vv = *(const float4*)(rowp + 2 * CDIM);
        *(float4*)(Ks + n * KSTR + d4) = kk;
        *(float4*)(Vs + n * KSTR + d4) = vv;
    }
    __syncthreads();

    const int w    = tid >> 5;            // 0..15
    const int lane = tid & 31;

    for (int i = w + 16 * half; i < TOK; i += 32) {
        // Stage scaled q row (scale = hd^-0.5 = 0.125)
        const float* qrow = base + (size_t)i * (3 * CDIM) + h * HD;
        float q0 = qrow[lane];
        float q1 = qrow[lane + 32];
        Qs[w * HD + lane]      = q0 * 0.125f;
        Qs[w * HD + lane + 32] = q1 * 0.125f;
        __syncwarp();

        const float* rpbrow = rpbh + (size_t)i * TOK;
        float s[7];
#pragma unroll
        for (int t = 0; t < 7; t++) {
            int j = lane + t * 32;
            float a = -3.0e38f;
            if (j < TOK) {
                const float4* kp = (const float4*)(Ks + j * KSTR);
                const float4* qp = (const float4*)(Qs + w * HD);
                float4 accv = make_float4(0.f, 0.f, 0.f, 0.f);
#pragma unroll
                for (int d = 0; d < 16; d++) {
                    float4 k4 = kp[d];
                    float4 q4 = qp[d];
                    accv.x += q4.x * k4.x;
                    accv.y += q4.y * k4.y;
                    accv.z += q4.z * k4.z;
                    accv.w += q4.w * k4.w;
                }
                a = (accv.x + accv.y) + (accv.z + accv.w) + rpbrow[j];
            }
            s[t] = a;
        }

        // Softmax (warp-wide)
        float m = s[0];
#pragma unroll
        for (int t = 1; t < 7; t++) m = fmaxf(m, s[t]);
#pragma unroll
        for (int o = 16; o > 0; o >>= 1) m = fmaxf(m, __shfl_xor_sync(0xffffffffu, m, o));

        float sum = 0.f;
#pragma unroll
        for (int t = 0; t < 7; t++) {
            int j = lane + t * 32;
            float e = (j < TOK) ? __expf(s[t] - m) : 0.f;
            s[t] = e;
            sum += e;
        }
#pragma unroll
        for (int o = 16; o > 0; o >>= 1) sum += __shfl_xor_sync(0xffffffffu, sum, o);
        float inv = __frcp_rn(sum);

#pragma unroll
        for (int t = 0; t < 7; t++) {
            int j = lane + t * 32;
            if (j < TOK) Ps[w * PSTR + j] = s[t] * inv;
        }
        __syncwarp();

        // PV: lane owns dims {lane, lane+32}; 8 independent FMA chains
        float a0 = 0.f, a1 = 0.f, b0 = 0.f, b1 = 0.f;
        float c0 = 0.f, c1 = 0.f, d0 = 0.f, d1 = 0.f;
        int j = 0;
        for (; j + 3 < TOK; j += 4) {
            float p0 = Ps[w * PSTR + j];
            float p1 = Ps[w * PSTR + j + 1];
            float p2 = Ps[w * PSTR + j + 2];
            float p3 = Ps[w * PSTR + j + 3];
            a0 += p0 * Vs[j * KSTR + lane];
            a1 += p0 * Vs[j * KSTR + lane + 32];
            b0 += p1 * Vs[(j + 1) * KSTR + lane];
            b1 += p1 * Vs[(j + 1) * KSTR + lane + 32];
            c0 += p2 * Vs[(j + 2) * KSTR + lane];
            c1 += p2 * Vs[(j + 2) * KSTR + lane + 32];
            d0 += p3 * Vs[(j + 3) * KSTR + lane];
            d1 += p3 * Vs[(j + 3) * KSTR + lane + 32];
        }
        for (; j < TOK; j++) {
            float p = Ps[w * PSTR + j];
            a0 += p * Vs[j * KSTR + lane];
            a1 += p * Vs[j * KSTR + lane + 32];
        }
        a0 += b0 + c0 + d0;
        a1 += b1 + c1 + d1;

        float* orow = out + ((size_t)b * TOK + i) * CDIM + h * HD;
        orow[lane]      = a0;
        orow[lane + 32] = a1;
        __syncwarp();
    }
}

// ---------------------------------------------------------------------------
// kernel_launch: bias+RPB prep -> QKV tGEMM -> fused attention -> proj tGEMM
// ---------------------------------------------------------------------------
extern "C" void kernel_launch(void* const* d_in, const int* in_sizes, int n_in,
                              void* d_out, int out_size) {
    const float* x      = (const float*)d_in[0];
    const float* qkv_w  = (const float*)d_in[1];
    const float* q_bias = (const float*)d_in[2];
    const float* v_bias = (const float*)d_in[3];
    const float* rpb    = (const float*)d_in[4];
    const float* proj_w = (const float*)d_in[5];
    const float* proj_b = (const float*)d_in[6];
    const int*   relidx = (const int*)d_in[7];
    float* out = (float*)d_out;

    void* qkv_ptr;  cudaGetSymbolAddress(&qkv_ptr,  g_qkv);
    void* att_ptr;  cudaGetSymbolAddress(&att_ptr,  g_att);
    void* bias_ptr; cudaGetSymbolAddress(&bias_ptr, g_bias);

    cudaFuncSetAttribute(tgemm_nt_kernel,
                         cudaFuncAttributeMaxDynamicSharedMemorySize, GEMM_SMEM_BYTES);
    cudaFuncSetAttribute(attn_kernel,
                         cudaFuncAttributeMaxDynamicSharedMemorySize, ATTN_SMEM_BYTES);

    // 1. Fused bias vector + dense RPB table (both tiny)
    build_bias_kernel<<<(3 * CDIM + 255) / 256, 256>>>(q_bias, v_bias);
    build_rpb_kernel<<<(TOK * TOK + 255) / 256, 256>>>(rpb, relidx);

    // 2. QKV GEMM (tf32 tensor): (12608 x 768) @ (2304 x 768)^T + bias
    {
        dim3 grid((3 * CDIM) / BN, (MTOT + BM - 1) / BM);
        tgemm_nt_kernel<<<grid, 256, GEMM_SMEM_BYTES>>>(
            x, qkv_w, (const float*)bias_ptr, (float*)qkv_ptr,
            MTOT, 3 * CDIM, CDIM);
    }

    // 3. Fused attention (1536 CTAs = B*H*2 row-halves, 512 threads)
    attn_kernel<<<BATCH * NH * 2, 512, ATTN_SMEM_BYTES>>>((const float*)qkv_ptr,
                                                          (float*)att_ptr);

    // 4. Proj GEMM (tf32 tensor): (12608 x 768) @ (768 x 768)^T + proj_b
    {
        dim3 grid(CDIM / BN, (MTOT + BM - 1) / BM);
        tgemm_nt_kernel<<<grid, 256, GEMM_SMEM_BYTES>>>(
            (const float*)att_ptr, proj_w, proj_b, out,
            MTOT, CDIM, CDIM);
    }
}